// round 15
// baseline (speedup 1.0000x reference)
#include <cuda_runtime.h>
#include <cuda_bf16.h>
#include <math.h>
#include <float.h>
#include <stdint.h>

#define N_NODES 50000
#define N_EDGES 600000
#define N_GRAPHS 512
#define HID 128
#define LAT 64
#define NL 4
#define NSLOT 10
#define NTILES 782          // ceil(N_NODES/64)
#define PGRID 296           // 2 CTAs x 148 SMs (persistent grid; all co-resident)
#define LTH 512             // layer kernel threads (16 warps, 4x4 warp grid)

// ======================= scratch =======================
__device__ float g_h[N_NODES * HID];
__device__ float g_t[N_NODES * HID];
__device__ float g_hs[NL][N_NODES * HID];
__device__ int   g_deg[N_NODES];
__device__ int   g_ptr[N_NODES + 1];
__device__ int   g_cursor[N_NODES];
__device__ int   g_srclist[N_EDGES];
__device__ int   g_bsum[64];
__device__ float g_sum[NSLOT * HID];
__device__ float g_sumsq[NSLOT * HID];
__device__ float g_psum[N_GRAPHS * HID];
__device__ float g_pmax[N_GRAPHS * HID];
__device__ int   g_pcnt[N_GRAPHS];
__device__ int   g_tilec[NL * 2];
__device__ int   g_syncc[12];
__device__ unsigned char g_wsplit[8][65536];

__device__ __forceinline__ float gelu_exact(float x) {
    return 0.5f * x * (1.0f + erff(x * 0.70710678118654752f));
}
__device__ __forceinline__ void atomicMaxF(float* addr, float v) {
    if (__float_as_int(v) >= 0) atomicMax((int*)addr, __float_as_int(v));
    else atomicMin((unsigned int*)addr, __float_as_uint(v));
}
__device__ __forceinline__ uint32_t smem_u32(const void* p) {
    uint32_t a;
    asm("{ .reg .u64 t; cvta.to.shared.u64 t, %1; cvt.u32.u64 %0, t; }" : "=r"(a) : "l"(p));
    return a;
}

#define LDMATRIX_X4(r, addr) \
    asm volatile("ldmatrix.sync.aligned.m8n8.x4.shared.b16 {%0,%1,%2,%3}, [%4];" \
        : "=r"((r)[0]), "=r"((r)[1]), "=r"((r)[2]), "=r"((r)[3]) : "r"(addr))

#define MMA16816(c, a, b) \
    asm volatile("mma.sync.aligned.m16n8k16.row.col.f32.bf16.bf16.f32 " \
        "{%0,%1,%2,%3}, {%4,%5,%6,%7}, {%8,%9}, {%0,%1,%2,%3};" \
        : "+f"((c)[0]), "+f"((c)[1]), "+f"((c)[2]), "+f"((c)[3]) \
        : "r"((a)[0]), "r"((a)[1]), "r"((a)[2]), "r"((a)[3]), "r"((b)[0]), "r"((b)[1]))

__device__ __forceinline__ void finalize_cg(int slot, const float* gamma,
                                            const float* beta,
                                            float* sScale, float* sShift, int tid) {
    if (tid < HID) {
        const float invN = 1.0f / N_NODES;
        float mean = __ldcg(&g_sum[slot * HID + tid]) * invN;
        float var  = __ldcg(&g_sumsq[slot * HID + tid]) * invN - mean * mean;
        float sc = __ldg(&gamma[tid]) * rsqrtf(var + 1e-5f);
        sScale[tid] = sc;
        sShift[tid] = __ldg(&beta[tid]) - mean * sc;
    }
}

// grid barrier: atomic arrive, volatile-load poll (no serializing atomics in spin)
__device__ __forceinline__ void grid_sync(int idx) {
    __syncthreads();
    if (threadIdx.x == 0) {
        __threadfence();
        atomicAdd(&g_syncc[idx], 1);
        volatile int* p = &g_syncc[idx];
        while (*p < PGRID) __nanosleep(64);
        __threadfence();
    }
    __syncthreads();
}

// ======== merged prep: zero-init + weight split + input colstats ============
#define PREP_ZERO 256
#define PREP_WS 64
#define PREP_CS 256
__global__ void prep_kernel(const float* __restrict__ x,
                            const float* __restrict__ fc1_w,
                            const float* __restrict__ fc2_w) {
    int b = blockIdx.x, tid = threadIdx.x;
    if (b < PREP_ZERO) {
        int i = b * 256 + tid;
        if (i < NSLOT * HID) { g_sum[i] = 0.f; g_sumsq[i] = 0.f; }
        if (i < N_NODES) g_deg[i] = 0;
        if (i < N_GRAPHS * HID) { g_psum[i] = 0.f; g_pmax[i] = -FLT_MAX; }
        if (i < N_GRAPHS) g_pcnt[i] = 0;
        if (i < NL * 2) g_tilec[i] = PGRID;
        if (i < 12) g_syncc[i] = 0;
    } else if (b < PREP_ZERO + PREP_WS) {
        int bb = b - PREP_ZERO;
        int w = bb >> 3;
        int l = w >> 1, which = w & 1;
        const float* W = (which ? fc2_w : fc1_w) + l * HID * HID;
        __nv_bfloat16* bh = (__nv_bfloat16*)(g_wsplit[w]);
        __nv_bfloat16* bl = (__nv_bfloat16*)(g_wsplit[w] + 32768);
        int chunk = bb & 7;
        for (int i = tid + chunk * 2048; i < (chunk + 1) * 2048; i += 256) {
            int n = i >> 7, k = i & 127;
            float v = W[k * HID + n];
            __nv_bfloat16 hi = __float2bfloat16_rn(v);
            bh[n * 128 + k] = hi;
            bl[n * 128 + k] = __float2bfloat16_rn(v - __bfloat162float(hi));
        }
    } else {
        int p = b - (PREP_ZERO + PREP_WS);
        int c = tid & 127;
        float s = 0.f, s2 = 0.f;
        for (int n = p * 2 + (tid >> 7); n < N_NODES; n += 512) {
            float v = x[n * HID + c];
            s += v; s2 += v * v;
        }
        atomicAdd(&g_sum[c], s);
        atomicAdd(&g_sumsq[c], s2);
    }
}

// ---------------- CSR build ----------------
__global__ void hist_kernel(const int* __restrict__ dst) {
    int i = blockIdx.x * blockDim.x + threadIdx.x;
    if (i < N_EDGES) atomicAdd(&g_deg[dst[i]], 1);
}

__global__ void scan1_kernel() {
    __shared__ int s[1024];
    int tid = threadIdx.x;
    int i = blockIdx.x * 1024 + tid;
    int v = (i < N_NODES) ? g_deg[i] : 0;
    s[tid] = v;
    __syncthreads();
#pragma unroll
    for (int d = 1; d < 1024; d <<= 1) {
        int t = (tid >= d) ? s[tid - d] : 0;
        __syncthreads();
        s[tid] += t;
        __syncthreads();
    }
    if (i < N_NODES) g_cursor[i] = s[tid];
    if (tid == 1023) g_bsum[blockIdx.x] = s[tid];
}

__global__ void scan3_kernel() {
    __shared__ int boff;
    if (threadIdx.x == 0) {
        int s = 0;
        for (int k = 0; k < blockIdx.x; k++) s += g_bsum[k];
        boff = s;
    }
    __syncthreads();
    int i = blockIdx.x * 1024 + threadIdx.x;
    if (i < N_NODES) {
        int p = boff + g_cursor[i] - g_deg[i];
        g_ptr[i] = p;
        g_cursor[i] = p;
    }
    if (i == 0) g_ptr[N_NODES] = N_EDGES;
}

__global__ void scatter_kernel(const int* __restrict__ src, const int* __restrict__ dst) {
    int i = blockIdx.x * blockDim.x + threadIdx.x;
    if (i < N_EDGES) {
        int pos = atomicAdd(&g_cursor[dst[i]], 1);
        g_srclist[pos] = src[i];
    }
}

// ---------------- GEMM phase: 512 threads, warp grid 4(M) x 4(N) ------------
#define APAD 136
#define AT_BYTES (64 * APAD * 2)              // 17408
#define BT_BYTES (128 * APAD * 2)             // 34816
#define SM_AH 0
#define SM_AL AT_BYTES
#define SM_BH (2 * AT_BYTES)
#define SM_BL (2 * AT_BYTES + BT_BYTES)
#define SM_SC (2 * AT_BYTES + 2 * BT_BYTES)   // 104448
#define SM_SH (SM_SC + 512)
#define TC_SMEM (SM_SC + 1024)                // 105472 -> 2 CTAs/SM

template <int PRE>
__device__ __forceinline__ void gemm_phase(
    unsigned char* smem, uint32_t sb, int tid, int lane, int wid, int* s_tile_p,
    const float* __restrict__ A, int widx, const float* __restrict__ bias,
    float* __restrict__ C, int oslot, int* tile_ctr,
    const float* sScale, const float* sShift) {

    // B: copy pre-split B^T (hi+lo) once per CTA (512 threads)
    {
        const uint4* srcH = (const uint4*)(g_wsplit[widx]);
        const uint4* srcL = (const uint4*)(g_wsplit[widx] + 32768);
#pragma unroll
        for (int it = 0; it < 4; it++) {
            int i = tid + it * 512;
            int n = i >> 4, ss = i & 15;
            *(uint4*)(smem + SM_BH + n * (APAD * 2) + ss * 16) = __ldg(srcH + i);
            *(uint4*)(smem + SM_BL + n * (APAD * 2) + ss * 16) = __ldg(srcL + i);
        }
    }
    __syncthreads();

    int r = tid >> 3, qt = tid & 7;       // 8 threads/row, 16 cols each
    int wm = wid & 3, wn = wid >> 2;
    int mbase = wm * 16, nbase = wn * 32;
    int g = lane >> 2, tc = (lane & 3) * 2;
    int row0 = mbase + g;

    // bias preloaded into registers (loop-invariant)
    float bb0[4], bb1[4];
#pragma unroll
    for (int j = 0; j < 4; j++) {
        int col = nbase + j * 8 + tc;
        bb0[j] = __ldg(&bias[col]);
        bb1[j] = __ldg(&bias[col + 1]);
    }

    int t = blockIdx.x;
    while (t < NTILES) {
        int m0 = t * 64;
        if (tid == 0) *s_tile_p = atomicAdd(tile_ctr, 1);

        // A load: 4 independent float4 LDGs, convert+split
        {
            bool valid = (m0 + r) < N_NODES;
            const float4* Arow = (const float4*)(A + (size_t)(m0 + r) * HID) + qt * 4;
            float4 pf[4];
#pragma unroll
            for (int k = 0; k < 4; k++)
                pf[k] = valid ? __ldg(Arow + k) : make_float4(0.f, 0.f, 0.f, 0.f);
#pragma unroll
            for (int jj = 0; jj < 4; jj++) {
                int col = qt * 16 + jj * 4;
                float4 v = pf[jj];
                if (PRE) {
                    float4 sc = ((const float4*)sScale)[col >> 2];
                    float4 sh = ((const float4*)sShift)[col >> 2];
                    v.x = gelu_exact(v.x * sc.x + sh.x);
                    v.y = gelu_exact(v.y * sc.y + sh.y);
                    v.z = gelu_exact(v.z * sc.z + sh.z);
                    v.w = gelu_exact(v.w * sc.w + sh.w);
                }
                __nv_bfloat16 h0 = __float2bfloat16_rn(v.x), h1 = __float2bfloat16_rn(v.y);
                __nv_bfloat16 h2 = __float2bfloat16_rn(v.z), h3 = __float2bfloat16_rn(v.w);
                float l0 = v.x - __bfloat162float(h0), l1 = v.y - __bfloat162float(h1);
                float l2 = v.z - __bfloat162float(h2), l3 = v.w - __bfloat162float(h3);
                uint2 hp, lp;
                hp.x = (uint32_t)__bfloat16_as_ushort(h0) | ((uint32_t)__bfloat16_as_ushort(h1) << 16);
                hp.y = (uint32_t)__bfloat16_as_ushort(h2) | ((uint32_t)__bfloat16_as_ushort(h3) << 16);
                lp.x = (uint32_t)__bfloat16_as_ushort(__float2bfloat16_rn(l0)) |
                       ((uint32_t)__bfloat16_as_ushort(__float2bfloat16_rn(l1)) << 16);
                lp.y = (uint32_t)__bfloat16_as_ushort(__float2bfloat16_rn(l2)) |
                       ((uint32_t)__bfloat16_as_ushort(__float2bfloat16_rn(l3)) << 16);
                uint32_t off = r * (APAD * 2) + col * 2;
                *(uint2*)(smem + SM_AH + off) = hp;
                *(uint2*)(smem + SM_AL + off) = lp;
            }
        }
        __syncthreads();
        int t_next = *s_tile_p;

        // MMA mainloop: warp grid 4(M) x 4(N), warp tile 16x32
        float acc[4][4];
#pragma unroll
        for (int j = 0; j < 4; j++)
#pragma unroll
            for (int c = 0; c < 4; c++) acc[j][c] = 0.f;

        int q = lane >> 3, riq = lane & 7;
#pragma unroll
        for (int ks = 0; ks < 8; ks++) {
            uint32_t ah[4], al[4], bh[4][2], bl[4][2];
            {
                int row = mbase + (q & 1) * 8 + riq;
                int kb = ks * 16 + (q >> 1) * 8;
                uint32_t addr = sb + SM_AH + row * (APAD * 2) + kb * 2;
                LDMATRIX_X4(ah, addr);
                LDMATRIX_X4(al, addr + AT_BYTES);
            }
#pragma unroll
            for (int j = 0; j < 2; j++) {
                int n = nbase + j * 16 + (q >> 1) * 8 + riq;
                int kb = ks * 16 + (q & 1) * 8;
                uint32_t addr = sb + SM_BH + n * (APAD * 2) + kb * 2;
                uint32_t t4[4];
                LDMATRIX_X4(t4, addr);
                bh[j * 2][0] = t4[0]; bh[j * 2][1] = t4[1];
                bh[j * 2 + 1][0] = t4[2]; bh[j * 2 + 1][1] = t4[3];
                LDMATRIX_X4(t4, addr + BT_BYTES);
                bl[j * 2][0] = t4[0]; bl[j * 2][1] = t4[1];
                bl[j * 2 + 1][0] = t4[2]; bl[j * 2 + 1][1] = t4[3];
            }
#pragma unroll
            for (int j = 0; j < 4; j++) {
                MMA16816(acc[j], ah, bh[j]);
                MMA16816(acc[j], ah, bl[j]);
                MMA16816(acc[j], al, bh[j]);
            }
        }
        __syncthreads();   // A consumed; reuse A region as C staging

        float* sC = (float*)smem;
        {
#pragma unroll
            for (int j = 0; j < 4; j++) {
                int col = nbase + j * 8 + tc;
                sC[row0 * 132 + col]           = acc[j][0] + bb0[j];
                sC[row0 * 132 + col + 1]       = acc[j][1] + bb1[j];
                sC[(row0 + 8) * 132 + col]     = acc[j][2] + bb0[j];
                sC[(row0 + 8) * 132 + col + 1] = acc[j][3] + bb1[j];
            }
        }

        // register stats: column sum/sumsq via xor-shuffle over row lanes (stride 4)
        {
            float r0f = (m0 + row0 < N_NODES) ? 1.f : 0.f;
            float r1f = (m0 + row0 + 8 < N_NODES) ? 1.f : 0.f;
#pragma unroll
            for (int j = 0; j < 4; j++) {
                float v0 = acc[j][0] + bb0[j], v1 = acc[j][1] + bb1[j];
                float v2 = acc[j][2] + bb0[j], v3 = acc[j][3] + bb1[j];
                float s0 = v0 * r0f + v2 * r1f;
                float q0 = v0 * v0 * r0f + v2 * v2 * r1f;
                float s1 = v1 * r0f + v3 * r1f;
                float q1 = v1 * v1 * r0f + v3 * v3 * r1f;
#pragma unroll
                for (int off = 4; off < 32; off <<= 1) {
                    s0 += __shfl_xor_sync(0xffffffffu, s0, off);
                    q0 += __shfl_xor_sync(0xffffffffu, q0, off);
                    s1 += __shfl_xor_sync(0xffffffffu, s1, off);
                    q1 += __shfl_xor_sync(0xffffffffu, q1, off);
                }
                if (lane < 4) {
                    int col = nbase + j * 8 + tc;
                    atomicAdd(&g_sum[oslot * HID + col], s0);
                    atomicAdd(&g_sumsq[oslot * HID + col], q0);
                    atomicAdd(&g_sum[oslot * HID + col + 1], s1);
                    atomicAdd(&g_sumsq[oslot * HID + col + 1], q1);
                }
            }
        }
        __syncthreads();

        // coalesced STG from staging
        {
            int r2 = tid >> 3, qt2 = tid & 7;
            if (m0 + r2 < N_NODES) {
                float4* dst = (float4*)(C + (size_t)(m0 + r2) * HID + qt2 * 16);
                const float4* src2 = (const float4*)(sC + r2 * 132 + qt2 * 16);
#pragma unroll
                for (int i = 0; i < 4; i++) dst[i] = src2[i];
            }
        }
        __syncthreads();   // sC reads done before next convert overwrites
        t = t_next;
    }
}

// ---------------- whole layer: agg -> GEMM1 -> GEMM2 -> BN ------------------
template <int L0>
__global__ void __launch_bounds__(LTH, 2)
layer_kernel(const float* __restrict__ Ain, int layer,
             const float* __restrict__ eps,
             const float* __restrict__ ibn_g, const float* __restrict__ ibn_b,
             const float* __restrict__ fc1_b,
             const float* __restrict__ bn1_g, const float* __restrict__ bn1_b,
             const float* __restrict__ fc2_b,
             const float* __restrict__ bn_g, const float* __restrict__ bn_b,
             float* __restrict__ hs_out) {
    extern __shared__ unsigned char smem[];
    __shared__ int s_tile;
    int tid = threadIdx.x, lane = tid & 31, wid = tid >> 5;
    uint32_t sb = smem_u32(smem);
    float* sScale = (float*)(smem + SM_SC);
    float* sShift = (float*)(smem + SM_SH);
    int s1 = 1 + 2 * layer, s2 = 2 + 2 * layer;

    // ===== phase 0: GIN aggregation (warp per node, 16 warps/CTA) =====
    if (L0) {
        finalize_cg(0, ibn_g, ibn_b, sScale, sShift, tid);
        __syncthreads();
    }
    {
        float ev = __ldg(&eps[layer]);
        float op = 1.0f + ev;
        float4 sc4, sh4;
        if (L0) { sc4 = ((const float4*)sScale)[lane]; sh4 = ((const float4*)sShift)[lane]; }
        for (int n = blockIdx.x * 16 + wid; n < N_NODES; n += PGRID * 16) {
            float4 a = __ldg((const float4*)(Ain + (size_t)n * HID) + lane);
            float4 acc = make_float4(op * a.x, op * a.y, op * a.z, op * a.w);
            int b = g_ptr[n], e = g_ptr[n + 1];
            int j = b;
            for (; j + 1 < e; j += 2) {
                int q0 = g_srclist[j], q1 = g_srclist[j + 1];
                float4 v0 = __ldg((const float4*)(Ain + (size_t)q0 * HID) + lane);
                float4 v1 = __ldg((const float4*)(Ain + (size_t)q1 * HID) + lane);
                acc.x += v0.x + v1.x; acc.y += v0.y + v1.y;
                acc.z += v0.z + v1.z; acc.w += v0.w + v1.w;
            }
            if (j < e) {
                float4 v0 = __ldg((const float4*)(Ain + (size_t)g_srclist[j] * HID) + lane);
                acc.x += v0.x; acc.y += v0.y; acc.z += v0.z; acc.w += v0.w;
            }
            if (L0) {
                float shf = op + (float)(e - b);
                acc.x = sc4.x * acc.x + shf * sh4.x;
                acc.y = sc4.y * acc.y + shf * sh4.y;
                acc.z = sc4.z * acc.z + shf * sh4.z;
                acc.w = sc4.w * acc.w + shf * sh4.w;
            }
            *((float4*)(g_h + (size_t)n * HID) + lane) = acc;
        }
    }
    grid_sync(layer * 3 + 0);

    // ===== phase 1: GEMM1 =====
    gemm_phase<0>(smem, sb, tid, lane, wid, &s_tile,
                  g_h, layer * 2, fc1_b, g_t, s1, &g_tilec[layer * 2],
                  sScale, sShift);
    grid_sync(layer * 3 + 1);

    // ===== phase 2: GEMM2 (BN(s1)+GELU fused on A) =====
    finalize_cg(s1, bn1_g, bn1_b, sScale, sShift, tid);
    gemm_phase<1>(smem, sb, tid, lane, wid, &s_tile,
                  g_t, layer * 2 + 1, fc2_b, g_t, s2, &g_tilec[layer * 2 + 1],
                  sScale, sShift);
    grid_sync(layer * 3 + 2);

    // ===== phase 3: BN(s2)+GELU -> hs_out =====
    finalize_cg(s2, bn_g, bn_b, sScale, sShift, tid);
    __syncthreads();
    {
        const int total = N_NODES * HID / 4;
        for (int idx = blockIdx.x * LTH + tid; idx < total; idx += PGRID * LTH) {
            int c4 = idx & 31;
            float4 v;
            v.x = __ldcg(g_t + idx * 4);
            v.y = __ldcg(g_t + idx * 4 + 1);
            v.z = __ldcg(g_t + idx * 4 + 2);
            v.w = __ldcg(g_t + idx * 4 + 3);
            float4 sc = ((const float4*)sScale)[c4];
            float4 sh = ((const float4*)sShift)[c4];
            v.x = gelu_exact(v.x * sc.x + sh.x);
            v.y = gelu_exact(v.y * sc.y + sh.y);
            v.z = gelu_exact(v.z * sc.z + sh.z);
            v.w = gelu_exact(v.w * sc.w + sh.w);
            ((float4*)hs_out)[idx] = v;
        }
    }
}

// ---------------- fused JK attention + pooling ----------------
#define JKP_BLOCKS 500
#define JKP_WARPS (JKP_BLOCKS * 8)
__global__ void jk_pool_kernel(const int* __restrict__ batch, const float* __restrict__ att) {
    int wgid = blockIdx.x * 8 + (threadIdx.x >> 5);
    int lane = threadIdx.x & 31;
    const int CH = (N_NODES + JKP_WARPS - 1) / JKP_WARPS;   // 13
    int n0 = wgid * CH, n1 = min(n0 + CH, N_NODES);
    if (n0 >= n1) return;
    int c0 = lane * 4;

    float4 attc[NL];
#pragma unroll
    for (int l = 0; l < NL; l++)
        attc[l] = __ldg((const float4*)(att + l * HID) + lane);

    int g = __ldg(&batch[n0]);
    float4 s4 = make_float4(0.f, 0.f, 0.f, 0.f);
    float4 m4 = make_float4(-FLT_MAX, -FLT_MAX, -FLT_MAX, -FLT_MAX);
    int cnt = 0;

    for (int n = n0; n < n1; n++) {
        int gn = __ldg(&batch[n]);
        if (gn != g) {
            if (cnt > 0) {
                atomicAdd(&g_psum[g * HID + c0], s4.x);
                atomicAdd(&g_psum[g * HID + c0 + 1], s4.y);
                atomicAdd(&g_psum[g * HID + c0 + 2], s4.z);
                atomicAdd(&g_psum[g * HID + c0 + 3], s4.w);
                atomicMaxF(&g_pmax[g * HID + c0], m4.x);
                atomicMaxF(&g_pmax[g * HID + c0 + 1], m4.y);
                atomicMaxF(&g_pmax[g * HID + c0 + 2], m4.z);
                atomicMaxF(&g_pmax[g * HID + c0 + 3], m4.w);
                if (lane == 0) atomicAdd(&g_pcnt[g], cnt);
            }
            g = gn;
            s4 = make_float4(0.f, 0.f, 0.f, 0.f);
            m4 = make_float4(-FLT_MAX, -FLT_MAX, -FLT_MAX, -FLT_MAX);
            cnt = 0;
        }
        float4 v[NL];
        float p[NL];
#pragma unroll
        for (int l = 0; l < NL; l++) {
            v[l] = *(const float4*)(&g_hs[l][(size_t)n * HID + c0]);
            p[l] = v[l].x * attc[l].x + v[l].y * attc[l].y +
                   v[l].z * attc[l].z + v[l].w * attc[l].w;
        }
#pragma unroll
        for (int off = 16; off; off >>= 1) {
#pragma unroll
            for (int l = 0; l < NL; l++)
                p[l] += __shfl_xor_sync(0xffffffffu, p[l], off);
        }
        float m = fmaxf(fmaxf(p[0], p[1]), fmaxf(p[2], p[3]));
        float e[NL], tot = 0.f;
#pragma unroll
        for (int l = 0; l < NL; l++) {
            e[l] = expf((p[l] - m) * (1.0f / HID));
            tot += e[l];
        }
        float inv = 1.0f / tot;
        float4 xc = make_float4(0.f, 0.f, 0.f, 0.f);
#pragma unroll
        for (int l = 0; l < NL; l++) {
            float w = e[l] * inv;
            xc.x += w * v[l].x; xc.y += w * v[l].y;
            xc.z += w * v[l].z; xc.w += w * v[l].w;
        }
        s4.x += xc.x; s4.y += xc.y; s4.z += xc.z; s4.w += xc.w;
        m4.x = fmaxf(m4.x, xc.x); m4.y = fmaxf(m4.y, xc.y);
        m4.z = fmaxf(m4.z, xc.z); m4.w = fmaxf(m4.w, xc.w);
        cnt++;
    }
    if (cnt > 0) {
        atomicAdd(&g_psum[g * HID + c0], s4.x);
        atomicAdd(&g_psum[g * HID + c0 + 1], s4.y);
        atomicAdd(&g_psum[g * HID + c0 + 2], s4.z);
        atomicAdd(&g_psum[g * HID + c0 + 3], s4.w);
        atomicMaxF(&g_pmax[g * HID + c0], m4.x);
        atomicMaxF(&g_pmax[g * HID + c0 + 1], m4.y);
        atomicMaxF(&g_pmax[g * HID + c0 + 2], m4.z);
        atomicMaxF(&g_pmax[g * HID + c0 + 3], m4.w);
        if (lane == 0) atomicAdd(&g_pcnt[g], cnt);
    }
}

// ---------------- head ----------------
__global__ void head_kernel(const float* __restrict__ pwraw,
                            const float* __restrict__ fcA_w, const float* __restrict__ fcA_b,
                            const float* __restrict__ ln_g, const float* __restrict__ ln_b,
                            const float* __restrict__ fcB_w, const float* __restrict__ fcB_b,
                            float* __restrict__ out) {
    __shared__ float sp[HID];
    __shared__ float sh[HID];
    __shared__ float red[HID];
    int g = blockIdx.x, c = threadIdx.x;

    float w0 = pwraw[0], w1 = pwraw[1], w2 = pwraw[2];
    float mw = fmaxf(w0, fmaxf(w1, w2));
    float e0 = expf(w0 - mw), e1 = expf(w1 - mw), e2 = expf(w2 - mw);
    float et = 1.0f / (e0 + e1 + e2);
    float pw0 = e0 * et, pw1 = e1 * et, pw2 = e2 * et;

    float cnt = (float)g_pcnt[g];
    float s = g_psum[g * HID + c];
    float mean = s / fmaxf(cnt, 1.0f);
    float mx = (cnt > 0.f) ? g_pmax[g * HID + c] : 0.0f;
    float pooled = s * pw0 + mean * pw1 + mx * pw2;
    sp[c] = pooled;
    __syncthreads();

    float acc = fcA_b[c];
#pragma unroll 8
    for (int k = 0; k < HID; k++) acc += sp[k] * fcA_w[k * HID + c];

    red[c] = acc;
    __syncthreads();
    for (int st = 64; st > 0; st >>= 1) { if (c < st) red[c] += red[c + st]; __syncthreads(); }
    float mu = red[0] * (1.0f / HID);
    __syncthreads();
    float d = acc - mu;
    red[c] = d * d;
    __syncthreads();
    for (int st = 64; st > 0; st >>= 1) { if (c < st) red[c] += red[c + st]; __syncthreads(); }
    float var = red[0] * (1.0f / HID);
    float y = d * rsqrtf(var + 1e-5f) * ln_g[c] + ln_b[c];
    float h = gelu_exact(y) + pooled;
    sh[c] = h;
    __syncthreads();

    if (c < LAT) {
        float o = fcB_b[c];
#pragma unroll 8
        for (int k = 0; k < HID; k++) o += sh[k] * fcB_w[k * LAT + c];
        out[g * LAT + c] = o;
    }
}

// ---------------- launcher ----------------
extern "C" void kernel_launch(void* const* d_in, const int* in_sizes, int n_in,
                              void* d_out, int out_size) {
    const float* x      = (const float*)d_in[0];
    const int*   ei     = (const int*)d_in[1];
    const int*   batch  = (const int*)d_in[2];
    const float* ibn_g  = (const float*)d_in[3];
    const float* ibn_b  = (const float*)d_in[4];
    const float* eps    = (const float*)d_in[5];
    const float* fc1_w  = (const float*)d_in[6];
    const float* fc1_b  = (const float*)d_in[7];
    const float* bn1_g  = (const float*)d_in[8];
    const float* bn1_b  = (const float*)d_in[9];
    const float* fc2_w  = (const float*)d_in[10];
    const float* fc2_b  = (const float*)d_in[11];
    const float* bn_g   = (const float*)d_in[12];
    const float* bn_b   = (const float*)d_in[13];
    const float* att_w  = (const float*)d_in[14];
    const float* pool_w = (const float*)d_in[15];
    const float* fcA_w  = (const float*)d_in[16];
    const float* fcA_b  = (const float*)d_in[17];
    const float* ln_g   = (const float*)d_in[18];
    const float* ln_b   = (const float*)d_in[19];
    const float* fcB_w  = (const float*)d_in[20];
    const float* fcB_b  = (const float*)d_in[21];
    float* out = (float*)d_out;

    const int* srcp = ei;
    const int* dstp = ei + N_EDGES;

    cudaFuncSetAttribute((const void*)layer_kernel<1>,
                         cudaFuncAttributeMaxDynamicSharedMemorySize, TC_SMEM);
    cudaFuncSetAttribute((const void*)layer_kernel<0>,
                         cudaFuncAttributeMaxDynamicSharedMemorySize, TC_SMEM);

    float* p_hs;
    cudaGetSymbolAddress((void**)&p_hs, g_hs);

    const int SCAN_GRID = (N_NODES + 1023) / 1024;

    prep_kernel<<<PREP_ZERO + PREP_WS + PREP_CS, 256>>>(x, fc1_w, fc2_w);
    hist_kernel<<<(N_EDGES + 511) / 512, 512>>>(dstp);
    scan1_kernel<<<SCAN_GRID, 1024>>>();
    scan3_kernel<<<SCAN_GRID, 1024>>>();
    scatter_kernel<<<(N_EDGES + 511) / 512, 512>>>(srcp, dstp);

    layer_kernel<1><<<PGRID, LTH, TC_SMEM>>>(
        x, 0, eps, ibn_g, ibn_b,
        fc1_b, bn1_g, bn1_b, fc2_b, bn_g, bn_b, p_hs);
    for (int l = 1; l < NL; l++) {
        layer_kernel<0><<<PGRID, LTH, TC_SMEM>>>(
            p_hs + (size_t)(l - 1) * N_NODES * HID, l, eps, nullptr, nullptr,
            fc1_b + l * HID, bn1_g + l * HID, bn1_b + l * HID,
            fc2_b + l * HID, bn_g + l * HID, bn_b + l * HID,
            p_hs + (size_t)l * N_NODES * HID);
    }

    jk_pool_kernel<<<JKP_BLOCKS, 256>>>(batch, att_w);
    head_kernel<<<N_GRAPHS, 128>>>(pool_w, fcA_w, fcA_b, ln_g, ln_b, fcB_w, fcB_b, out);
}

// round 16
// speedup vs baseline: 1.1960x; 1.1960x over previous
#include <cuda_runtime.h>
#include <cuda_bf16.h>
#include <math.h>
#include <float.h>
#include <stdint.h>

#define N_NODES 50000
#define N_EDGES 600000
#define N_GRAPHS 512
#define HID 128
#define LAT 64
#define NL 4
#define NSLOT 10
#define NTILES 782          // ceil(N_NODES/64)
#define PGRID 296           // 2 CTAs x 148 SMs (persistent grid; all co-resident)
#define LTH 512             // layer kernel threads (16 warps, 4x4 warp grid)

// ======================= scratch =======================
__device__ float g_h[N_NODES * HID];
__device__ float g_t[N_NODES * HID];
__device__ float g_hs[NL][N_NODES * HID];
__device__ int   g_deg[N_NODES];
__device__ int   g_ptr[N_NODES + 1];
__device__ int   g_cursor[N_NODES];
__device__ int   g_srclist[N_EDGES];
__device__ int   g_bsum[64];
__device__ float g_sum[NSLOT * HID];
__device__ float g_sumsq[NSLOT * HID];
__device__ float g_psum[N_GRAPHS * HID];
__device__ float g_pmax[N_GRAPHS * HID];
__device__ int   g_pcnt[N_GRAPHS];
__device__ int   g_tilec[NL * 2];
__device__ int   g_syncc[12];
__device__ unsigned char g_wsplit[8][65536];

__device__ __forceinline__ float gelu_exact(float x) {
    return 0.5f * x * (1.0f + erff(x * 0.70710678118654752f));
}
__device__ __forceinline__ void atomicMaxF(float* addr, float v) {
    if (__float_as_int(v) >= 0) atomicMax((int*)addr, __float_as_int(v));
    else atomicMin((unsigned int*)addr, __float_as_uint(v));
}
__device__ __forceinline__ uint32_t smem_u32(const void* p) {
    uint32_t a;
    asm("{ .reg .u64 t; cvta.to.shared.u64 t, %1; cvt.u32.u64 %0, t; }" : "=r"(a) : "l"(p));
    return a;
}

#define LDMATRIX_X4(r, addr) \
    asm volatile("ldmatrix.sync.aligned.m8n8.x4.shared.b16 {%0,%1,%2,%3}, [%4];" \
        : "=r"((r)[0]), "=r"((r)[1]), "=r"((r)[2]), "=r"((r)[3]) : "r"(addr))

#define MMA16816(c, a, b) \
    asm volatile("mma.sync.aligned.m16n8k16.row.col.f32.bf16.bf16.f32 " \
        "{%0,%1,%2,%3}, {%4,%5,%6,%7}, {%8,%9}, {%0,%1,%2,%3};" \
        : "+f"((c)[0]), "+f"((c)[1]), "+f"((c)[2]), "+f"((c)[3]) \
        : "r"((a)[0]), "r"((a)[1]), "r"((a)[2]), "r"((a)[3]), "r"((b)[0]), "r"((b)[1]))

__device__ __forceinline__ void finalize_cg(int slot, const float* gamma,
                                            const float* beta,
                                            float* sScale, float* sShift, int tid) {
    if (tid < HID) {
        const float invN = 1.0f / N_NODES;
        float mean = __ldcg(&g_sum[slot * HID + tid]) * invN;
        float var  = __ldcg(&g_sumsq[slot * HID + tid]) * invN - mean * mean;
        float sc = __ldg(&gamma[tid]) * rsqrtf(var + 1e-5f);
        sScale[tid] = sc;
        sShift[tid] = __ldg(&beta[tid]) - mean * sc;
    }
}

__device__ __forceinline__ void grid_sync(int idx) {
    __syncthreads();
    if (threadIdx.x == 0) {
        __threadfence();
        atomicAdd(&g_syncc[idx], 1);
        while (atomicAdd(&g_syncc[idx], 0) < PGRID) __nanosleep(64);
        __threadfence();
    }
    __syncthreads();
}

// ======== merged prep: zero-init + weight split + input colstats ============
#define PREP_ZERO 256
#define PREP_WS 64
#define PREP_CS 256
__global__ void prep_kernel(const float* __restrict__ x,
                            const float* __restrict__ fc1_w,
                            const float* __restrict__ fc2_w) {
    int b = blockIdx.x, tid = threadIdx.x;
    if (b < PREP_ZERO) {
        int i = b * 256 + tid;
        if (i < NSLOT * HID) { g_sum[i] = 0.f; g_sumsq[i] = 0.f; }
        if (i < N_NODES) g_deg[i] = 0;
        if (i < N_GRAPHS * HID) { g_psum[i] = 0.f; g_pmax[i] = -FLT_MAX; }
        if (i < N_GRAPHS) g_pcnt[i] = 0;
        if (i < NL * 2) g_tilec[i] = PGRID;
        if (i < 12) g_syncc[i] = 0;
    } else if (b < PREP_ZERO + PREP_WS) {
        int bb = b - PREP_ZERO;
        int w = bb >> 3;
        int l = w >> 1, which = w & 1;
        const float* W = (which ? fc2_w : fc1_w) + l * HID * HID;
        __nv_bfloat16* bh = (__nv_bfloat16*)(g_wsplit[w]);
        __nv_bfloat16* bl = (__nv_bfloat16*)(g_wsplit[w] + 32768);
        int chunk = bb & 7;
        for (int i = tid + chunk * 2048; i < (chunk + 1) * 2048; i += 256) {
            int n = i >> 7, k = i & 127;
            float v = W[k * HID + n];
            __nv_bfloat16 hi = __float2bfloat16_rn(v);
            bh[n * 128 + k] = hi;
            bl[n * 128 + k] = __float2bfloat16_rn(v - __bfloat162float(hi));
        }
    } else {
        int p = b - (PREP_ZERO + PREP_WS);
        int c = tid & 127;
        float s = 0.f, s2 = 0.f;
        for (int n = p * 2 + (tid >> 7); n < N_NODES; n += 512) {
            float v = x[n * HID + c];
            s += v; s2 += v * v;
        }
        atomicAdd(&g_sum[c], s);
        atomicAdd(&g_sumsq[c], s2);
    }
}

// ---------------- CSR build ----------------
__global__ void hist_kernel(const int* __restrict__ dst) {
    int i = blockIdx.x * blockDim.x + threadIdx.x;
    if (i < N_EDGES) atomicAdd(&g_deg[dst[i]], 1);
}

__global__ void scan1_kernel() {
    __shared__ int s[1024];
    int tid = threadIdx.x;
    int i = blockIdx.x * 1024 + tid;
    int v = (i < N_NODES) ? g_deg[i] : 0;
    s[tid] = v;
    __syncthreads();
#pragma unroll
    for (int d = 1; d < 1024; d <<= 1) {
        int t = (tid >= d) ? s[tid - d] : 0;
        __syncthreads();
        s[tid] += t;
        __syncthreads();
    }
    if (i < N_NODES) g_cursor[i] = s[tid];
    if (tid == 1023) g_bsum[blockIdx.x] = s[tid];
}

__global__ void scan3_kernel() {
    __shared__ int boff;
    if (threadIdx.x == 0) {
        int s = 0;
        for (int k = 0; k < blockIdx.x; k++) s += g_bsum[k];
        boff = s;
    }
    __syncthreads();
    int i = blockIdx.x * 1024 + threadIdx.x;
    if (i < N_NODES) {
        int p = boff + g_cursor[i] - g_deg[i];
        g_ptr[i] = p;
        g_cursor[i] = p;
    }
    if (i == 0) g_ptr[N_NODES] = N_EDGES;
}

__global__ void scatter_kernel(const int* __restrict__ src, const int* __restrict__ dst) {
    int i = blockIdx.x * blockDim.x + threadIdx.x;
    if (i < N_EDGES) {
        int pos = atomicAdd(&g_cursor[dst[i]], 1);
        g_srclist[pos] = src[i];
    }
}

// ---------------- GEMM phase: 512 threads, warp grid 4(M) x 4(N) ------------
#define APAD 136
#define AT_BYTES (64 * APAD * 2)              // 17408
#define BT_BYTES (128 * APAD * 2)             // 34816
#define SM_AH 0
#define SM_AL AT_BYTES
#define SM_BH (2 * AT_BYTES)
#define SM_BL (2 * AT_BYTES + BT_BYTES)
#define SM_SC (2 * AT_BYTES + 2 * BT_BYTES)   // 104448
#define SM_SH (SM_SC + 512)
#define TC_SMEM (SM_SC + 1024)                // 105472 -> 2 CTAs/SM

template <int PRE>
__device__ __forceinline__ void gemm_phase(
    unsigned char* smem, uint32_t sb, int tid, int lane, int wid, int* s_tile_p,
    const float* __restrict__ A, int widx, const float* __restrict__ bias,
    float* __restrict__ C, int oslot, int* tile_ctr,
    const float* sScale, const float* sShift) {

    // B: copy pre-split B^T (hi+lo) once per CTA (512 threads)
    {
        const uint4* srcH = (const uint4*)(g_wsplit[widx]);
        const uint4* srcL = (const uint4*)(g_wsplit[widx] + 32768);
#pragma unroll
        for (int it = 0; it < 4; it++) {
            int i = tid + it * 512;
            int n = i >> 4, ss = i & 15;
            *(uint4*)(smem + SM_BH + n * (APAD * 2) + ss * 16) = __ldg(srcH + i);
            *(uint4*)(smem + SM_BL + n * (APAD * 2) + ss * 16) = __ldg(srcL + i);
        }
    }
    __syncthreads();

    int r = tid >> 3, qt = tid & 7;       // 8 threads/row, 16 cols each
    int t = blockIdx.x;

    while (t < NTILES) {
        int m0 = t * 64;
        if (tid == 0) *s_tile_p = atomicAdd(tile_ctr, 1);

        // A load: 4 independent float4 LDGs, convert+split
        {
            bool valid = (m0 + r) < N_NODES;
            const float4* Arow = (const float4*)(A + (size_t)(m0 + r) * HID) + qt * 4;
            float4 pf[4];
#pragma unroll
            for (int k = 0; k < 4; k++)
                pf[k] = valid ? __ldg(Arow + k) : make_float4(0.f, 0.f, 0.f, 0.f);
#pragma unroll
            for (int jj = 0; jj < 4; jj++) {
                int col = qt * 16 + jj * 4;
                float4 v = pf[jj];
                if (PRE) {
                    float4 sc = ((const float4*)sScale)[col >> 2];
                    float4 sh = ((const float4*)sShift)[col >> 2];
                    v.x = gelu_exact(v.x * sc.x + sh.x);
                    v.y = gelu_exact(v.y * sc.y + sh.y);
                    v.z = gelu_exact(v.z * sc.z + sh.z);
                    v.w = gelu_exact(v.w * sc.w + sh.w);
                }
                __nv_bfloat16 h0 = __float2bfloat16_rn(v.x), h1 = __float2bfloat16_rn(v.y);
                __nv_bfloat16 h2 = __float2bfloat16_rn(v.z), h3 = __float2bfloat16_rn(v.w);
                float l0 = v.x - __bfloat162float(h0), l1 = v.y - __bfloat162float(h1);
                float l2 = v.z - __bfloat162float(h2), l3 = v.w - __bfloat162float(h3);
                uint2 hp, lp;
                hp.x = (uint32_t)__bfloat16_as_ushort(h0) | ((uint32_t)__bfloat16_as_ushort(h1) << 16);
                hp.y = (uint32_t)__bfloat16_as_ushort(h2) | ((uint32_t)__bfloat16_as_ushort(h3) << 16);
                lp.x = (uint32_t)__bfloat16_as_ushort(__float2bfloat16_rn(l0)) |
                       ((uint32_t)__bfloat16_as_ushort(__float2bfloat16_rn(l1)) << 16);
                lp.y = (uint32_t)__bfloat16_as_ushort(__float2bfloat16_rn(l2)) |
                       ((uint32_t)__bfloat16_as_ushort(__float2bfloat16_rn(l3)) << 16);
                uint32_t off = r * (APAD * 2) + col * 2;
                *(uint2*)(smem + SM_AH + off) = hp;
                *(uint2*)(smem + SM_AL + off) = lp;
            }
        }
        __syncthreads();
        int t_next = *s_tile_p;

        // MMA mainloop: warp grid 4(M) x 4(N), warp tile 16x32
        int wm = wid & 3, wn = wid >> 2;
        int mbase = wm * 16, nbase = wn * 32;
        float acc[4][4];
#pragma unroll
        for (int j = 0; j < 4; j++)
#pragma unroll
            for (int c = 0; c < 4; c++) acc[j][c] = 0.f;

        int q = lane >> 3, riq = lane & 7;
#pragma unroll
        for (int ks = 0; ks < 8; ks++) {
            uint32_t ah[4], al[4], bh[4][2], bl[4][2];
            {
                int row = mbase + (q & 1) * 8 + riq;
                int kb = ks * 16 + (q >> 1) * 8;
                uint32_t addr = sb + SM_AH + row * (APAD * 2) + kb * 2;
                LDMATRIX_X4(ah, addr);
                LDMATRIX_X4(al, addr + AT_BYTES);
            }
#pragma unroll
            for (int j = 0; j < 2; j++) {
                int n = nbase + j * 16 + (q >> 1) * 8 + riq;
                int kb = ks * 16 + (q & 1) * 8;
                uint32_t addr = sb + SM_BH + n * (APAD * 2) + kb * 2;
                uint32_t t4[4];
                LDMATRIX_X4(t4, addr);
                bh[j * 2][0] = t4[0]; bh[j * 2][1] = t4[1];
                bh[j * 2 + 1][0] = t4[2]; bh[j * 2 + 1][1] = t4[3];
                LDMATRIX_X4(t4, addr + BT_BYTES);
                bl[j * 2][0] = t4[0]; bl[j * 2][1] = t4[1];
                bl[j * 2 + 1][0] = t4[2]; bl[j * 2 + 1][1] = t4[3];
            }
#pragma unroll
            for (int j = 0; j < 4; j++) {
                MMA16816(acc[j], ah, bh[j]);
                MMA16816(acc[j], ah, bl[j]);
                MMA16816(acc[j], al, bh[j]);
            }
        }
        __syncthreads();   // A consumed; reuse A region as C staging

        float* sC = (float*)smem;
        int g = lane >> 2, tc = (lane & 3) * 2;
        {
            int row0 = mbase + g;
#pragma unroll
            for (int j = 0; j < 4; j++) {
                int col = nbase + j * 8 + tc;
                float b0 = __ldg(&bias[col]), b1 = __ldg(&bias[col + 1]);
                sC[row0 * 132 + col]           = acc[j][0] + b0;
                sC[row0 * 132 + col + 1]       = acc[j][1] + b1;
                sC[(row0 + 8) * 132 + col]     = acc[j][2] + b0;
                sC[(row0 + 8) * 132 + col + 1] = acc[j][3] + b1;
            }
        }
        __syncthreads();

        {
            int r2 = tid >> 3, qt2 = tid & 7;
            if (m0 + r2 < N_NODES) {
                float4* dst = (float4*)(C + (size_t)(m0 + r2) * HID + qt2 * 16);
                const float4* src2 = (const float4*)(sC + r2 * 132 + qt2 * 16);
#pragma unroll
                for (int i = 0; i < 4; i++) dst[i] = src2[i];
            }
        }
        {
            int nrows = min(64, N_NODES - m0);
            int c = tid & 127;
            int rbeg = (tid >> 7) * 16;
            int rend = min(rbeg + 16, nrows);
            float s = 0.f, s2 = 0.f;
            for (int rr = rbeg; rr < rend; rr++) {
                float v = sC[rr * 132 + c];
                s += v; s2 += v * v;
            }
            atomicAdd(&g_sum[oslot * HID + c], s);
            atomicAdd(&g_sumsq[oslot * HID + c], s2);
        }
        __syncthreads();
        t = t_next;
    }
}

// ---------------- whole layer: agg -> GEMM1 -> GEMM2 -> BN ------------------
template <int L0>
__global__ void __launch_bounds__(LTH, 2)
layer_kernel(const float* __restrict__ Ain, int layer,
             const float* __restrict__ eps,
             const float* __restrict__ ibn_g, const float* __restrict__ ibn_b,
             const float* __restrict__ fc1_b,
             const float* __restrict__ bn1_g, const float* __restrict__ bn1_b,
             const float* __restrict__ fc2_b,
             const float* __restrict__ bn_g, const float* __restrict__ bn_b,
             float* __restrict__ hs_out) {
    extern __shared__ unsigned char smem[];
    __shared__ int s_tile;
    int tid = threadIdx.x, lane = tid & 31, wid = tid >> 5;
    uint32_t sb = smem_u32(smem);
    float* sScale = (float*)(smem + SM_SC);
    float* sShift = (float*)(smem + SM_SH);
    int s1 = 1 + 2 * layer, s2 = 2 + 2 * layer;

    // ===== phase 0: GIN aggregation (warp per node, 16 warps/CTA) =====
    if (L0) {
        finalize_cg(0, ibn_g, ibn_b, sScale, sShift, tid);
        __syncthreads();
    }
    {
        float ev = __ldg(&eps[layer]);
        float op = 1.0f + ev;
        float4 sc4, sh4;
        if (L0) { sc4 = ((const float4*)sScale)[lane]; sh4 = ((const float4*)sShift)[lane]; }
        for (int n = blockIdx.x * 16 + wid; n < N_NODES; n += PGRID * 16) {
            float4 a = __ldg((const float4*)(Ain + (size_t)n * HID) + lane);
            float4 acc = make_float4(op * a.x, op * a.y, op * a.z, op * a.w);
            int b = g_ptr[n], e = g_ptr[n + 1];
            int j = b;
            for (; j + 1 < e; j += 2) {
                int q0 = g_srclist[j], q1 = g_srclist[j + 1];
                float4 v0 = __ldg((const float4*)(Ain + (size_t)q0 * HID) + lane);
                float4 v1 = __ldg((const float4*)(Ain + (size_t)q1 * HID) + lane);
                acc.x += v0.x + v1.x; acc.y += v0.y + v1.y;
                acc.z += v0.z + v1.z; acc.w += v0.w + v1.w;
            }
            if (j < e) {
                float4 v0 = __ldg((const float4*)(Ain + (size_t)g_srclist[j] * HID) + lane);
                acc.x += v0.x; acc.y += v0.y; acc.z += v0.z; acc.w += v0.w;
            }
            if (L0) {
                float shf = op + (float)(e - b);
                acc.x = sc4.x * acc.x + shf * sh4.x;
                acc.y = sc4.y * acc.y + shf * sh4.y;
                acc.z = sc4.z * acc.z + shf * sh4.z;
                acc.w = sc4.w * acc.w + shf * sh4.w;
            }
            *((float4*)(g_h + (size_t)n * HID) + lane) = acc;
        }
    }
    grid_sync(layer * 3 + 0);

    // ===== phase 1: GEMM1 =====
    gemm_phase<0>(smem, sb, tid, lane, wid, &s_tile,
                  g_h, layer * 2, fc1_b, g_t, s1, &g_tilec[layer * 2],
                  sScale, sShift);
    grid_sync(layer * 3 + 1);

    // ===== phase 2: GEMM2 (BN(s1)+GELU fused on A) =====
    finalize_cg(s1, bn1_g, bn1_b, sScale, sShift, tid);
    gemm_phase<1>(smem, sb, tid, lane, wid, &s_tile,
                  g_t, layer * 2 + 1, fc2_b, g_t, s2, &g_tilec[layer * 2 + 1],
                  sScale, sShift);
    grid_sync(layer * 3 + 2);

    // ===== phase 3: BN(s2)+GELU -> hs_out =====
    finalize_cg(s2, bn_g, bn_b, sScale, sShift, tid);
    __syncthreads();
    {
        const int total = N_NODES * HID / 4;
        for (int idx = blockIdx.x * LTH + tid; idx < total; idx += PGRID * LTH) {
            int c4 = idx & 31;
            float4 v;
            v.x = __ldcg(g_t + idx * 4);
            v.y = __ldcg(g_t + idx * 4 + 1);
            v.z = __ldcg(g_t + idx * 4 + 2);
            v.w = __ldcg(g_t + idx * 4 + 3);
            float4 sc = ((const float4*)sScale)[c4];
            float4 sh = ((const float4*)sShift)[c4];
            v.x = gelu_exact(v.x * sc.x + sh.x);
            v.y = gelu_exact(v.y * sc.y + sh.y);
            v.z = gelu_exact(v.z * sc.z + sh.z);
            v.w = gelu_exact(v.w * sc.w + sh.w);
            ((float4*)hs_out)[idx] = v;
        }
    }
}

// ---------------- fused JK attention + pooling ----------------
#define JKP_BLOCKS 500
#define JKP_WARPS (JKP_BLOCKS * 8)
__global__ void jk_pool_kernel(const int* __restrict__ batch, const float* __restrict__ att) {
    int wgid = blockIdx.x * 8 + (threadIdx.x >> 5);
    int lane = threadIdx.x & 31;
    const int CH = (N_NODES + JKP_WARPS - 1) / JKP_WARPS;   // 13
    int n0 = wgid * CH, n1 = min(n0 + CH, N_NODES);
    if (n0 >= n1) return;
    int c0 = lane * 4;

    float4 attc[NL];
#pragma unroll
    for (int l = 0; l < NL; l++)
        attc[l] = __ldg((const float4*)(att + l * HID) + lane);

    int g = __ldg(&batch[n0]);
    float4 s4 = make_float4(0.f, 0.f, 0.f, 0.f);
    float4 m4 = make_float4(-FLT_MAX, -FLT_MAX, -FLT_MAX, -FLT_MAX);
    int cnt = 0;

    for (int n = n0; n < n1; n++) {
        int gn = __ldg(&batch[n]);
        if (gn != g) {
            if (cnt > 0) {
                atomicAdd(&g_psum[g * HID + c0], s4.x);
                atomicAdd(&g_psum[g * HID + c0 + 1], s4.y);
                atomicAdd(&g_psum[g * HID + c0 + 2], s4.z);
                atomicAdd(&g_psum[g * HID + c0 + 3], s4.w);
                atomicMaxF(&g_pmax[g * HID + c0], m4.x);
                atomicMaxF(&g_pmax[g * HID + c0 + 1], m4.y);
                atomicMaxF(&g_pmax[g * HID + c0 + 2], m4.z);
                atomicMaxF(&g_pmax[g * HID + c0 + 3], m4.w);
                if (lane == 0) atomicAdd(&g_pcnt[g], cnt);
            }
            g = gn;
            s4 = make_float4(0.f, 0.f, 0.f, 0.f);
            m4 = make_float4(-FLT_MAX, -FLT_MAX, -FLT_MAX, -FLT_MAX);
            cnt = 0;
        }
        float4 v[NL];
        float p[NL];
#pragma unroll
        for (int l = 0; l < NL; l++) {
            v[l] = *(const float4*)(&g_hs[l][(size_t)n * HID + c0]);
            p[l] = v[l].x * attc[l].x + v[l].y * attc[l].y +
                   v[l].z * attc[l].z + v[l].w * attc[l].w;
        }
#pragma unroll
        for (int off = 16; off; off >>= 1) {
#pragma unroll
            for (int l = 0; l < NL; l++)
                p[l] += __shfl_xor_sync(0xffffffffu, p[l], off);
        }
        float m = fmaxf(fmaxf(p[0], p[1]), fmaxf(p[2], p[3]));
        float e[NL], tot = 0.f;
#pragma unroll
        for (int l = 0; l < NL; l++) {
            e[l] = expf((p[l] - m) * (1.0f / HID));
            tot += e[l];
        }
        float inv = 1.0f / tot;
        float4 xc = make_float4(0.f, 0.f, 0.f, 0.f);
#pragma unroll
        for (int l = 0; l < NL; l++) {
            float w = e[l] * inv;
            xc.x += w * v[l].x; xc.y += w * v[l].y;
            xc.z += w * v[l].z; xc.w += w * v[l].w;
        }
        s4.x += xc.x; s4.y += xc.y; s4.z += xc.z; s4.w += xc.w;
        m4.x = fmaxf(m4.x, xc.x); m4.y = fmaxf(m4.y, xc.y);
        m4.z = fmaxf(m4.z, xc.z); m4.w = fmaxf(m4.w, xc.w);
        cnt++;
    }
    if (cnt > 0) {
        atomicAdd(&g_psum[g * HID + c0], s4.x);
        atomicAdd(&g_psum[g * HID + c0 + 1], s4.y);
        atomicAdd(&g_psum[g * HID + c0 + 2], s4.z);
        atomicAdd(&g_psum[g * HID + c0 + 3], s4.w);
        atomicMaxF(&g_pmax[g * HID + c0], m4.x);
        atomicMaxF(&g_pmax[g * HID + c0 + 1], m4.y);
        atomicMaxF(&g_pmax[g * HID + c0 + 2], m4.z);
        atomicMaxF(&g_pmax[g * HID + c0 + 3], m4.w);
        if (lane == 0) atomicAdd(&g_pcnt[g], cnt);
    }
}

// ---------------- head ----------------
__global__ void head_kernel(const float* __restrict__ pwraw,
                            const float* __restrict__ fcA_w, const float* __restrict__ fcA_b,
                            const float* __restrict__ ln_g, const float* __restrict__ ln_b,
                            const float* __restrict__ fcB_w, const float* __restrict__ fcB_b,
                            float* __restrict__ out) {
    __shared__ float sp[HID];
    __shared__ float sh[HID];
    __shared__ float red[HID];
    int g = blockIdx.x, c = threadIdx.x;

    float w0 = pwraw[0], w1 = pwraw[1], w2 = pwraw[2];
    float mw = fmaxf(w0, fmaxf(w1, w2));
    float e0 = expf(w0 - mw), e1 = expf(w1 - mw), e2 = expf(w2 - mw);
    float et = 1.0f / (e0 + e1 + e2);
    float pw0 = e0 * et, pw1 = e1 * et, pw2 = e2 * et;

    float cnt = (float)g_pcnt[g];
    float s = g_psum[g * HID + c];
    float mean = s / fmaxf(cnt, 1.0f);
    float mx = (cnt > 0.f) ? g_pmax[g * HID + c] : 0.0f;
    float pooled = s * pw0 + mean * pw1 + mx * pw2;
    sp[c] = pooled;
    __syncthreads();

    float acc = fcA_b[c];
#pragma unroll 8
    for (int k = 0; k < HID; k++) acc += sp[k] * fcA_w[k * HID + c];

    red[c] = acc;
    __syncthreads();
    for (int st = 64; st > 0; st >>= 1) { if (c < st) red[c] += red[c + st]; __syncthreads(); }
    float mu = red[0] * (1.0f / HID);
    __syncthreads();
    float d = acc - mu;
    red[c] = d * d;
    __syncthreads();
    for (int st = 64; st > 0; st >>= 1) { if (c < st) red[c] += red[c + st]; __syncthreads(); }
    float var = red[0] * (1.0f / HID);
    float y = d * rsqrtf(var + 1e-5f) * ln_g[c] + ln_b[c];
    float h = gelu_exact(y) + pooled;
    sh[c] = h;
    __syncthreads();

    if (c < LAT) {
        float o = fcB_b[c];
#pragma unroll 8
        for (int k = 0; k < HID; k++) o += sh[k] * fcB_w[k * LAT + c];
        out[g * LAT + c] = o;
    }
}

// ---------------- launcher ----------------
extern "C" void kernel_launch(void* const* d_in, const int* in_sizes, int n_in,
                              void* d_out, int out_size) {
    const float* x      = (const float*)d_in[0];
    const int*   ei     = (const int*)d_in[1];
    const int*   batch  = (const int*)d_in[2];
    const float* ibn_g  = (const float*)d_in[3];
    const float* ibn_b  = (const float*)d_in[4];
    const float* eps    = (const float*)d_in[5];
    const float* fc1_w  = (const float*)d_in[6];
    const float* fc1_b  = (const float*)d_in[7];
    const float* bn1_g  = (const float*)d_in[8];
    const float* bn1_b  = (const float*)d_in[9];
    const float* fc2_w  = (const float*)d_in[10];
    const float* fc2_b  = (const float*)d_in[11];
    const float* bn_g   = (const float*)d_in[12];
    const float* bn_b   = (const float*)d_in[13];
    const float* att_w  = (const float*)d_in[14];
    const float* pool_w = (const float*)d_in[15];
    const float* fcA_w  = (const float*)d_in[16];
    const float* fcA_b  = (const float*)d_in[17];
    const float* ln_g   = (const float*)d_in[18];
    const float* ln_b   = (const float*)d_in[19];
    const float* fcB_w  = (const float*)d_in[20];
    const float* fcB_b  = (const float*)d_in[21];
    float* out = (float*)d_out;

    const int* srcp = ei;
    const int* dstp = ei + N_EDGES;

    cudaFuncSetAttribute((const void*)layer_kernel<1>,
                         cudaFuncAttributeMaxDynamicSharedMemorySize, TC_SMEM);
    cudaFuncSetAttribute((const void*)layer_kernel<0>,
                         cudaFuncAttributeMaxDynamicSharedMemorySize, TC_SMEM);

    float* p_hs;
    cudaGetSymbolAddress((void**)&p_hs, g_hs);

    const int SCAN_GRID = (N_NODES + 1023) / 1024;

    prep_kernel<<<PREP_ZERO + PREP_WS + PREP_CS, 256>>>(x, fc1_w, fc2_w);
    hist_kernel<<<(N_EDGES + 511) / 512, 512>>>(dstp);
    scan1_kernel<<<SCAN_GRID, 1024>>>();
    scan3_kernel<<<SCAN_GRID, 1024>>>();
    scatter_kernel<<<(N_EDGES + 511) / 512, 512>>>(srcp, dstp);

    layer_kernel<1><<<PGRID, LTH, TC_SMEM>>>(
        x, 0, eps, ibn_g, ibn_b,
        fc1_b, bn1_g, bn1_b, fc2_b, bn_g, bn_b, p_hs);
    for (int l = 1; l < NL; l++) {
        layer_kernel<0><<<PGRID, LTH, TC_SMEM>>>(
            p_hs + (size_t)(l - 1) * N_NODES * HID, l, eps, nullptr, nullptr,
            fc1_b + l * HID, bn1_g + l * HID, bn1_b + l * HID,
            fc2_b + l * HID, bn_g + l * HID, bn_b + l * HID,
            p_hs + (size_t)l * N_NODES * HID);
    }

    jk_pool_kernel<<<JKP_BLOCKS, 256>>>(batch, att_w);
    head_kernel<<<N_GRAPHS, 128>>>(pool_w, fcA_w, fcA_b, ln_g, ln_b, fcB_w, fcB_b, out);
}

// round 17
// speedup vs baseline: 1.2039x; 1.0066x over previous
#include <cuda_runtime.h>
#include <cuda_bf16.h>
#include <math.h>
#include <float.h>
#include <stdint.h>

#define N_NODES 50000
#define N_EDGES 600000
#define N_GRAPHS 512
#define HID 128
#define LAT 64
#define NL 4
#define NSLOT 10
#define NTILES 782          // ceil(N_NODES/64)
#define PGRID 296           // 2 CTAs x 148 SMs (persistent grid; all co-resident)
#define LTH 512             // layer kernel threads (16 warps, 4x4 warp grid)

// ======================= scratch =======================
__device__ float g_h[N_NODES * HID];
__device__ float g_t[N_NODES * HID];
__device__ float g_hs[NL][N_NODES * HID];
__device__ int   g_deg[N_NODES];
__device__ int   g_ptr[N_NODES + 1];
__device__ int   g_cursor[N_NODES];
__device__ int   g_srclist[N_EDGES];
__device__ int   g_bsum[64];
__device__ float g_sum[NSLOT * HID];
__device__ float g_sumsq[NSLOT * HID];
__device__ float g_psum[N_GRAPHS * HID];
__device__ float g_pmax[N_GRAPHS * HID];
__device__ int   g_pcnt[N_GRAPHS];
__device__ int   g_tilec[NL * 2];
__device__ int   g_syncc[16];
__device__ unsigned char g_wsplit[8][65536];

__device__ __forceinline__ float gelu_exact(float x) {
    return 0.5f * x * (1.0f + erff(x * 0.70710678118654752f));
}
__device__ __forceinline__ void atomicMaxF(float* addr, float v) {
    if (__float_as_int(v) >= 0) atomicMax((int*)addr, __float_as_int(v));
    else atomicMin((unsigned int*)addr, __float_as_uint(v));
}
__device__ __forceinline__ uint32_t smem_u32(const void* p) {
    uint32_t a;
    asm("{ .reg .u64 t; cvta.to.shared.u64 t, %1; cvt.u32.u64 %0, t; }" : "=r"(a) : "l"(p));
    return a;
}

#define LDMATRIX_X4(r, addr) \
    asm volatile("ldmatrix.sync.aligned.m8n8.x4.shared.b16 {%0,%1,%2,%3}, [%4];" \
        : "=r"((r)[0]), "=r"((r)[1]), "=r"((r)[2]), "=r"((r)[3]) : "r"(addr))

#define MMA16816(c, a, b) \
    asm volatile("mma.sync.aligned.m16n8k16.row.col.f32.bf16.bf16.f32 " \
        "{%0,%1,%2,%3}, {%4,%5,%6,%7}, {%8,%9}, {%0,%1,%2,%3};" \
        : "+f"((c)[0]), "+f"((c)[1]), "+f"((c)[2]), "+f"((c)[3]) \
        : "r"((a)[0]), "r"((a)[1]), "r"((a)[2]), "r"((a)[3]), "r"((b)[0]), "r"((b)[1]))

__device__ __forceinline__ void finalize_cg(int slot, const float* gamma,
                                            const float* beta,
                                            float* sScale, float* sShift, int tid) {
    if (tid < HID) {
        const float invN = 1.0f / N_NODES;
        float mean = __ldcg(&g_sum[slot * HID + tid]) * invN;
        float var  = __ldcg(&g_sumsq[slot * HID + tid]) * invN - mean * mean;
        float sc = __ldg(&gamma[tid]) * rsqrtf(var + 1e-5f);
        sScale[tid] = sc;
        sShift[tid] = __ldg(&beta[tid]) - mean * sc;
    }
}

__device__ __forceinline__ void grid_sync(int idx) {
    __syncthreads();
    if (threadIdx.x == 0) {
        __threadfence();
        atomicAdd(&g_syncc[idx], 1);
        while (atomicAdd(&g_syncc[idx], 0) < PGRID) __nanosleep(64);
        __threadfence();
    }
    __syncthreads();
}

// ======== merged prep: zero-init + weight split + input colstats ============
#define PREP_ZERO 256
#define PREP_WS 64
#define PREP_CS 256
__global__ void prep_kernel(const float* __restrict__ x,
                            const float* __restrict__ fc1_w,
                            const float* __restrict__ fc2_w) {
    int b = blockIdx.x, tid = threadIdx.x;
    if (b < PREP_ZERO) {
        int i = b * 256 + tid;
        if (i < NSLOT * HID) { g_sum[i] = 0.f; g_sumsq[i] = 0.f; }
        if (i < N_NODES) g_deg[i] = 0;
        if (i < N_GRAPHS * HID) { g_psum[i] = 0.f; g_pmax[i] = -FLT_MAX; }
        if (i < N_GRAPHS) g_pcnt[i] = 0;
        if (i < NL * 2) g_tilec[i] = PGRID;
        if (i < 16) g_syncc[i] = 0;
    } else if (b < PREP_ZERO + PREP_WS) {
        int bb = b - PREP_ZERO;
        int w = bb >> 3;
        int l = w >> 1, which = w & 1;
        const float* W = (which ? fc2_w : fc1_w) + l * HID * HID;
        __nv_bfloat16* bh = (__nv_bfloat16*)(g_wsplit[w]);
        __nv_bfloat16* bl = (__nv_bfloat16*)(g_wsplit[w] + 32768);
        int chunk = bb & 7;
        for (int i = tid + chunk * 2048; i < (chunk + 1) * 2048; i += 256) {
            int n = i >> 7, k = i & 127;
            float v = W[k * HID + n];
            __nv_bfloat16 hi = __float2bfloat16_rn(v);
            bh[n * 128 + k] = hi;
            bl[n * 128 + k] = __float2bfloat16_rn(v - __bfloat162float(hi));
        }
    } else {
        int p = b - (PREP_ZERO + PREP_WS);
        int c = tid & 127;
        float s = 0.f, s2 = 0.f;
        for (int n = p * 2 + (tid >> 7); n < N_NODES; n += 512) {
            float v = x[n * HID + c];
            s += v; s2 += v * v;
        }
        atomicAdd(&g_sum[c], s);
        atomicAdd(&g_sumsq[c], s2);
    }
}

// ---------------- CSR build ----------------
__global__ void hist_kernel(const int* __restrict__ dst) {
    int i = blockIdx.x * blockDim.x + threadIdx.x;
    if (i < N_EDGES) atomicAdd(&g_deg[dst[i]], 1);
}

__global__ void scan1_kernel() {
    __shared__ int s[1024];
    int tid = threadIdx.x;
    int i = blockIdx.x * 1024 + tid;
    int v = (i < N_NODES) ? g_deg[i] : 0;
    s[tid] = v;
    __syncthreads();
#pragma unroll
    for (int d = 1; d < 1024; d <<= 1) {
        int t = (tid >= d) ? s[tid - d] : 0;
        __syncthreads();
        s[tid] += t;
        __syncthreads();
    }
    if (i < N_NODES) g_cursor[i] = s[tid];
    if (tid == 1023) g_bsum[blockIdx.x] = s[tid];
}

__global__ void scan3_kernel() {
    __shared__ int boff;
    if (threadIdx.x < 32) {
        int s = 0;
        for (int k = threadIdx.x; k < blockIdx.x; k += 32) s += g_bsum[k];
#pragma unroll
        for (int off = 16; off; off >>= 1) s += __shfl_down_sync(0xffffffffu, s, off);
        if (threadIdx.x == 0) boff = s;
    }
    __syncthreads();
    int i = blockIdx.x * 1024 + threadIdx.x;
    if (i < N_NODES) {
        int p = boff + g_cursor[i] - g_deg[i];
        g_ptr[i] = p;
        g_cursor[i] = p;
    }
    if (i == 0) g_ptr[N_NODES] = N_EDGES;
}

__global__ void scatter_kernel(const int* __restrict__ src, const int* __restrict__ dst) {
    int i = blockIdx.x * blockDim.x + threadIdx.x;
    if (i < N_EDGES) {
        int pos = atomicAdd(&g_cursor[dst[i]], 1);
        g_srclist[pos] = src[i];
    }
}

// ---------------- GEMM phase: 512 threads, warp grid 4(M) x 4(N) ------------
// A-loads use __ldcg: within the merged multi-layer kernel, g_h/g_t are
// rewritten each layer and plain __ldg could hit stale L1 lines cached by
// the previous layer's phase. (A rows have no reuse, so skipping L1 is free.)
#define APAD 136
#define AT_BYTES (64 * APAD * 2)              // 17408
#define BT_BYTES (128 * APAD * 2)             // 34816
#define SM_AH 0
#define SM_AL AT_BYTES
#define SM_BH (2 * AT_BYTES)
#define SM_BL (2 * AT_BYTES + BT_BYTES)
#define SM_SC (2 * AT_BYTES + 2 * BT_BYTES)   // 104448
#define SM_SH (SM_SC + 512)
#define TC_SMEM (SM_SC + 1024)                // 105472 -> 2 CTAs/SM

template <int PRE>
__device__ __forceinline__ void gemm_phase(
    unsigned char* smem, uint32_t sb, int tid, int lane, int wid, int* s_tile_p,
    const float* __restrict__ A, int widx, const float* __restrict__ bias,
    float* __restrict__ C, int oslot, int* tile_ctr,
    const float* sScale, const float* sShift) {

    // B: copy pre-split B^T (hi+lo) once per CTA (512 threads)
    {
        const uint4* srcH = (const uint4*)(g_wsplit[widx]);
        const uint4* srcL = (const uint4*)(g_wsplit[widx] + 32768);
#pragma unroll
        for (int it = 0; it < 4; it++) {
            int i = tid + it * 512;
            int n = i >> 4, ss = i & 15;
            *(uint4*)(smem + SM_BH + n * (APAD * 2) + ss * 16) = __ldg(srcH + i);
            *(uint4*)(smem + SM_BL + n * (APAD * 2) + ss * 16) = __ldg(srcL + i);
        }
    }
    __syncthreads();

    int r = tid >> 3, qt = tid & 7;       // 8 threads/row, 16 cols each
    int t = blockIdx.x;

    while (t < NTILES) {
        int m0 = t * 64;
        if (tid == 0) *s_tile_p = atomicAdd(tile_ctr, 1);

        // A load: 4 independent float4 LDG.CGs, convert+split
        {
            bool valid = (m0 + r) < N_NODES;
            const float4* Arow = (const float4*)(A + (size_t)(m0 + r) * HID) + qt * 4;
            float4 pf[4];
#pragma unroll
            for (int k = 0; k < 4; k++)
                pf[k] = valid ? __ldcg(Arow + k) : make_float4(0.f, 0.f, 0.f, 0.f);
#pragma unroll
            for (int jj = 0; jj < 4; jj++) {
                int col = qt * 16 + jj * 4;
                float4 v = pf[jj];
                if (PRE) {
                    float4 sc = ((const float4*)sScale)[col >> 2];
                    float4 sh = ((const float4*)sShift)[col >> 2];
                    v.x = gelu_exact(v.x * sc.x + sh.x);
                    v.y = gelu_exact(v.y * sc.y + sh.y);
                    v.z = gelu_exact(v.z * sc.z + sh.z);
                    v.w = gelu_exact(v.w * sc.w + sh.w);
                }
                __nv_bfloat16 h0 = __float2bfloat16_rn(v.x), h1 = __float2bfloat16_rn(v.y);
                __nv_bfloat16 h2 = __float2bfloat16_rn(v.z), h3 = __float2bfloat16_rn(v.w);
                float l0 = v.x - __bfloat162float(h0), l1 = v.y - __bfloat162float(h1);
                float l2 = v.z - __bfloat162float(h2), l3 = v.w - __bfloat162float(h3);
                uint2 hp, lp;
                hp.x = (uint32_t)__bfloat16_as_ushort(h0) | ((uint32_t)__bfloat16_as_ushort(h1) << 16);
                hp.y = (uint32_t)__bfloat16_as_ushort(h2) | ((uint32_t)__bfloat16_as_ushort(h3) << 16);
                lp.x = (uint32_t)__bfloat16_as_ushort(__float2bfloat16_rn(l0)) |
                       ((uint32_t)__bfloat16_as_ushort(__float2bfloat16_rn(l1)) << 16);
                lp.y = (uint32_t)__bfloat16_as_ushort(__float2bfloat16_rn(l2)) |
                       ((uint32_t)__bfloat16_as_ushort(__float2bfloat16_rn(l3)) << 16);
                uint32_t off = r * (APAD * 2) + col * 2;
                *(uint2*)(smem + SM_AH + off) = hp;
                *(uint2*)(smem + SM_AL + off) = lp;
            }
        }
        __syncthreads();
        int t_next = *s_tile_p;

        // MMA mainloop: warp grid 4(M) x 4(N), warp tile 16x32
        int wm = wid & 3, wn = wid >> 2;
        int mbase = wm * 16, nbase = wn * 32;
        float acc[4][4];
#pragma unroll
        for (int j = 0; j < 4; j++)
#pragma unroll
            for (int c = 0; c < 4; c++) acc[j][c] = 0.f;

        int q = lane >> 3, riq = lane & 7;
#pragma unroll
        for (int ks = 0; ks < 8; ks++) {
            uint32_t ah[4], al[4], bh[4][2], bl[4][2];
            {
                int row = mbase + (q & 1) * 8 + riq;
                int kb = ks * 16 + (q >> 1) * 8;
                uint32_t addr = sb + SM_AH + row * (APAD * 2) + kb * 2;
                LDMATRIX_X4(ah, addr);
                LDMATRIX_X4(al, addr + AT_BYTES);
            }
#pragma unroll
            for (int j = 0; j < 2; j++) {
                int n = nbase + j * 16 + (q >> 1) * 8 + riq;
                int kb = ks * 16 + (q & 1) * 8;
                uint32_t addr = sb + SM_BH + n * (APAD * 2) + kb * 2;
                uint32_t t4[4];
                LDMATRIX_X4(t4, addr);
                bh[j * 2][0] = t4[0]; bh[j * 2][1] = t4[1];
                bh[j * 2 + 1][0] = t4[2]; bh[j * 2 + 1][1] = t4[3];
                LDMATRIX_X4(t4, addr + BT_BYTES);
                bl[j * 2][0] = t4[0]; bl[j * 2][1] = t4[1];
                bl[j * 2 + 1][0] = t4[2]; bl[j * 2 + 1][1] = t4[3];
            }
#pragma unroll
            for (int j = 0; j < 4; j++) {
                MMA16816(acc[j], ah, bh[j]);
                MMA16816(acc[j], ah, bl[j]);
                MMA16816(acc[j], al, bh[j]);
            }
        }
        __syncthreads();   // A consumed; reuse A region as C staging

        float* sC = (float*)smem;
        int g = lane >> 2, tc = (lane & 3) * 2;
        {
            int row0 = mbase + g;
#pragma unroll
            for (int j = 0; j < 4; j++) {
                int col = nbase + j * 8 + tc;
                float b0 = __ldg(&bias[col]), b1 = __ldg(&bias[col + 1]);
                sC[row0 * 132 + col]           = acc[j][0] + b0;
                sC[row0 * 132 + col + 1]       = acc[j][1] + b1;
                sC[(row0 + 8) * 132 + col]     = acc[j][2] + b0;
                sC[(row0 + 8) * 132 + col + 1] = acc[j][3] + b1;
            }
        }
        __syncthreads();

        {
            int r2 = tid >> 3, qt2 = tid & 7;
            if (m0 + r2 < N_NODES) {
                float4* dst = (float4*)(C + (size_t)(m0 + r2) * HID + qt2 * 16);
                const float4* src2 = (const float4*)(sC + r2 * 132 + qt2 * 16);
#pragma unroll
                for (int i = 0; i < 4; i++) dst[i] = src2[i];
            }
        }
        {
            int nrows = min(64, N_NODES - m0);
            int c = tid & 127;
            int rbeg = (tid >> 7) * 16;
            int rend = min(rbeg + 16, nrows);
            float s = 0.f, s2 = 0.f;
            for (int rr = rbeg; rr < rend; rr++) {
                float v = sC[rr * 132 + c];
                s += v; s2 += v * v;
            }
            atomicAdd(&g_sum[oslot * HID + c], s);
            atomicAdd(&g_sumsq[oslot * HID + c], s2);
        }
        __syncthreads();
        t = t_next;
    }
}

// ------- all 4 layers in ONE persistent launch (grid_sync between) ----------
__global__ void __launch_bounds__(LTH, 2)
layers_kernel(const float* __restrict__ x,
              const float* __restrict__ eps,
              const float* __restrict__ ibn_g, const float* __restrict__ ibn_b,
              const float* __restrict__ fc1_b_all,
              const float* __restrict__ bn1_g_all, const float* __restrict__ bn1_b_all,
              const float* __restrict__ fc2_b_all,
              const float* __restrict__ bn_g_all, const float* __restrict__ bn_b_all,
              float* __restrict__ hs_base) {
    extern __shared__ unsigned char smem[];
    __shared__ int s_tile;
    int tid = threadIdx.x, lane = tid & 31, wid = tid >> 5;
    uint32_t sb = smem_u32(smem);
    float* sScale = (float*)(smem + SM_SC);
    float* sShift = (float*)(smem + SM_SH);

    for (int layer = 0; layer < NL; layer++) {
        const float* Ain = (layer == 0) ? x : hs_base + (size_t)(layer - 1) * N_NODES * HID;
        float* hs_out = hs_base + (size_t)layer * N_NODES * HID;
        int s1 = 1 + 2 * layer, s2 = 2 + 2 * layer;
        bool l0 = (layer == 0);

        // ===== phase 0: GIN aggregation (warp per node; input-BN folded on l0) =====
        if (l0) {
            finalize_cg(0, ibn_g, ibn_b, sScale, sShift, tid);
            __syncthreads();
        }
        {
            float ev = __ldg(&eps[layer]);
            float op = 1.0f + ev;
            float4 sc4 = make_float4(1.f, 1.f, 1.f, 1.f);
            float4 sh4 = make_float4(0.f, 0.f, 0.f, 0.f);
            if (l0) { sc4 = ((const float4*)sScale)[lane]; sh4 = ((const float4*)sShift)[lane]; }
            for (int n = blockIdx.x * 16 + wid; n < N_NODES; n += PGRID * 16) {
                float4 a = __ldg((const float4*)(Ain + (size_t)n * HID) + lane);
                float4 acc = make_float4(op * a.x, op * a.y, op * a.z, op * a.w);
                int b = g_ptr[n], e = g_ptr[n + 1];
                int j = b;
                for (; j + 1 < e; j += 2) {
                    int q0 = g_srclist[j], q1 = g_srclist[j + 1];
                    float4 v0 = __ldg((const float4*)(Ain + (size_t)q0 * HID) + lane);
                    float4 v1 = __ldg((const float4*)(Ain + (size_t)q1 * HID) + lane);
                    acc.x += v0.x + v1.x; acc.y += v0.y + v1.y;
                    acc.z += v0.z + v1.z; acc.w += v0.w + v1.w;
                }
                if (j < e) {
                    float4 v0 = __ldg((const float4*)(Ain + (size_t)g_srclist[j] * HID) + lane);
                    acc.x += v0.x; acc.y += v0.y; acc.z += v0.z; acc.w += v0.w;
                }
                if (l0) {
                    float shf = op + (float)(e - b);
                    acc.x = sc4.x * acc.x + shf * sh4.x;
                    acc.y = sc4.y * acc.y + shf * sh4.y;
                    acc.z = sc4.z * acc.z + shf * sh4.z;
                    acc.w = sc4.w * acc.w + shf * sh4.w;
                }
                *((float4*)(g_h + (size_t)n * HID) + lane) = acc;
            }
        }
        grid_sync(layer * 4 + 0);

        // ===== phase 1: GEMM1 =====
        gemm_phase<0>(smem, sb, tid, lane, wid, &s_tile,
                      g_h, layer * 2, fc1_b_all + layer * HID, g_t, s1,
                      &g_tilec[layer * 2], sScale, sShift);
        grid_sync(layer * 4 + 1);

        // ===== phase 2: GEMM2 (BN(s1)+GELU fused on A) =====
        finalize_cg(s1, bn1_g_all + layer * HID, bn1_b_all + layer * HID,
                    sScale, sShift, tid);
        gemm_phase<1>(smem, sb, tid, lane, wid, &s_tile,
                      g_t, layer * 2 + 1, fc2_b_all + layer * HID, g_t, s2,
                      &g_tilec[layer * 2 + 1], sScale, sShift);
        grid_sync(layer * 4 + 2);

        // ===== phase 3: BN(s2)+GELU -> hs_out =====
        finalize_cg(s2, bn_g_all + layer * HID, bn_b_all + layer * HID,
                    sScale, sShift, tid);
        __syncthreads();
        {
            const int total = N_NODES * HID / 4;
            for (int idx = blockIdx.x * LTH + tid; idx < total; idx += PGRID * LTH) {
                int c4 = idx & 31;
                float4 v;
                v.x = __ldcg(g_t + idx * 4);
                v.y = __ldcg(g_t + idx * 4 + 1);
                v.z = __ldcg(g_t + idx * 4 + 2);
                v.w = __ldcg(g_t + idx * 4 + 3);
                float4 sc = ((const float4*)sScale)[c4];
                float4 sh = ((const float4*)sShift)[c4];
                v.x = gelu_exact(v.x * sc.x + sh.x);
                v.y = gelu_exact(v.y * sc.y + sh.y);
                v.z = gelu_exact(v.z * sc.z + sh.z);
                v.w = gelu_exact(v.w * sc.w + sh.w);
                ((float4*)hs_out)[idx] = v;
            }
        }
        if (layer < NL - 1) grid_sync(layer * 4 + 3);  // hs visible before next agg
    }
}

// ---------------- fused JK attention + pooling ----------------
#define JKP_BLOCKS 500
#define JKP_WARPS (JKP_BLOCKS * 8)
__global__ void jk_pool_kernel(const int* __restrict__ batch, const float* __restrict__ att) {
    int wgid = blockIdx.x * 8 + (threadIdx.x >> 5);
    int lane = threadIdx.x & 31;
    const int CH = (N_NODES + JKP_WARPS - 1) / JKP_WARPS;   // 13
    int n0 = wgid * CH, n1 = min(n0 + CH, N_NODES);
    if (n0 >= n1) return;
    int c0 = lane * 4;

    float4 attc[NL];
#pragma unroll
    for (int l = 0; l < NL; l++)
        attc[l] = __ldg((const float4*)(att + l * HID) + lane);

    int g = __ldg(&batch[n0]);
    float4 s4 = make_float4(0.f, 0.f, 0.f, 0.f);
    float4 m4 = make_float4(-FLT_MAX, -FLT_MAX, -FLT_MAX, -FLT_MAX);
    int cnt = 0;

    for (int n = n0; n < n1; n++) {
        int gn = __ldg(&batch[n]);
        if (gn != g) {
            if (cnt > 0) {
                atomicAdd(&g_psum[g * HID + c0], s4.x);
                atomicAdd(&g_psum[g * HID + c0 + 1], s4.y);
                atomicAdd(&g_psum[g * HID + c0 + 2], s4.z);
                atomicAdd(&g_psum[g * HID + c0 + 3], s4.w);
                atomicMaxF(&g_pmax[g * HID + c0], m4.x);
                atomicMaxF(&g_pmax[g * HID + c0 + 1], m4.y);
                atomicMaxF(&g_pmax[g * HID + c0 + 2], m4.z);
                atomicMaxF(&g_pmax[g * HID + c0 + 3], m4.w);
                if (lane == 0) atomicAdd(&g_pcnt[g], cnt);
            }
            g = gn;
            s4 = make_float4(0.f, 0.f, 0.f, 0.f);
            m4 = make_float4(-FLT_MAX, -FLT_MAX, -FLT_MAX, -FLT_MAX);
            cnt = 0;
        }
        float4 v[NL];
        float p[NL];
#pragma unroll
        for (int l = 0; l < NL; l++) {
            v[l] = *(const float4*)(&g_hs[l][(size_t)n * HID + c0]);
            p[l] = v[l].x * attc[l].x + v[l].y * attc[l].y +
                   v[l].z * attc[l].z + v[l].w * attc[l].w;
        }
#pragma unroll
        for (int off = 16; off; off >>= 1) {
#pragma unroll
            for (int l = 0; l < NL; l++)
                p[l] += __shfl_xor_sync(0xffffffffu, p[l], off);
        }
        float m = fmaxf(fmaxf(p[0], p[1]), fmaxf(p[2], p[3]));
        float e[NL], tot = 0.f;
#pragma unroll
        for (int l = 0; l < NL; l++) {
            e[l] = expf((p[l] - m) * (1.0f / HID));
            tot += e[l];
        }
        float inv = 1.0f / tot;
        float4 xc = make_float4(0.f, 0.f, 0.f, 0.f);
#pragma unroll
        for (int l = 0; l < NL; l++) {
            float w = e[l] * inv;
            xc.x += w * v[l].x; xc.y += w * v[l].y;
            xc.z += w * v[l].z; xc.w += w * v[l].w;
        }
        s4.x += xc.x; s4.y += xc.y; s4.z += xc.z; s4.w += xc.w;
        m4.x = fmaxf(m4.x, xc.x); m4.y = fmaxf(m4.y, xc.y);
        m4.z = fmaxf(m4.z, xc.z); m4.w = fmaxf(m4.w, xc.w);
        cnt++;
    }
    if (cnt > 0) {
        atomicAdd(&g_psum[g * HID + c0], s4.x);
        atomicAdd(&g_psum[g * HID + c0 + 1], s4.y);
        atomicAdd(&g_psum[g * HID + c0 + 2], s4.z);
        atomicAdd(&g_psum[g * HID + c0 + 3], s4.w);
        atomicMaxF(&g_pmax[g * HID + c0], m4.x);
        atomicMaxF(&g_pmax[g * HID + c0 + 1], m4.y);
        atomicMaxF(&g_pmax[g * HID + c0 + 2], m4.z);
        atomicMaxF(&g_pmax[g * HID + c0 + 3], m4.w);
        if (lane == 0) atomicAdd(&g_pcnt[g], cnt);
    }
}

// ---------------- head ----------------
__global__ void head_kernel(const float* __restrict__ pwraw,
                            const float* __restrict__ fcA_w, const float* __restrict__ fcA_b,
                            const float* __restrict__ ln_g, const float* __restrict__ ln_b,
                            const float* __restrict__ fcB_w, const float* __restrict__ fcB_b,
                            float* __restrict__ out) {
    __shared__ float sp[HID];
    __shared__ float sh[HID];
    __shared__ float red[HID];
    int g = blockIdx.x, c = threadIdx.x;

    float w0 = pwraw[0], w1 = pwraw[1], w2 = pwraw[2];
    float mw = fmaxf(w0, fmaxf(w1, w2));
    float e0 = expf(w0 - mw), e1 = expf(w1 - mw), e2 = expf(w2 - mw);
    float et = 1.0f / (e0 + e1 + e2);
    float pw0 = e0 * et, pw1 = e1 * et, pw2 = e2 * et;

    float cnt = (float)g_pcnt[g];
    float s = g_psum[g * HID + c];
    float mean = s / fmaxf(cnt, 1.0f);
    float mx = (cnt > 0.f) ? g_pmax[g * HID + c] : 0.0f;
    float pooled = s * pw0 + mean * pw1 + mx * pw2;
    sp[c] = pooled;
    __syncthreads();

    float acc = fcA_b[c];
#pragma unroll 8
    for (int k = 0; k < HID; k++) acc += sp[k] * fcA_w[k * HID + c];

    red[c] = acc;
    __syncthreads();
    for (int st = 64; st > 0; st >>= 1) { if (c < st) red[c] += red[c + st]; __syncthreads(); }
    float mu = red[0] * (1.0f / HID);
    __syncthreads();
    float d = acc - mu;
    red[c] = d * d;
    __syncthreads();
    for (int st = 64; st > 0; st >>= 1) { if (c < st) red[c] += red[c + st]; __syncthreads(); }
    float var = red[0] * (1.0f / HID);
    float y = d * rsqrtf(var + 1e-5f) * ln_g[c] + ln_b[c];
    float h = gelu_exact(y) + pooled;
    sh[c] = h;
    __syncthreads();

    if (c < LAT) {
        float o = fcB_b[c];
#pragma unroll 8
        for (int k = 0; k < HID; k++) o += sh[k] * fcB_w[k * LAT + c];
        out[g * LAT + c] = o;
    }
}

// ---------------- launcher ----------------
extern "C" void kernel_launch(void* const* d_in, const int* in_sizes, int n_in,
                              void* d_out, int out_size) {
    const float* x      = (const float*)d_in[0];
    const int*   ei     = (const int*)d_in[1];
    const int*   batch  = (const int*)d_in[2];
    const float* ibn_g  = (const float*)d_in[3];
    const float* ibn_b  = (const float*)d_in[4];
    const float* eps    = (const float*)d_in[5];
    const float* fc1_w  = (const float*)d_in[6];
    const float* fc1_b  = (const float*)d_in[7];
    const float* bn1_g  = (const float*)d_in[8];
    const float* bn1_b  = (const float*)d_in[9];
    const float* fc2_w  = (const float*)d_in[10];
    const float* fc2_b  = (const float*)d_in[11];
    const float* bn_g   = (const float*)d_in[12];
    const float* bn_b   = (const float*)d_in[13];
    const float* att_w  = (const float*)d_in[14];
    const float* pool_w = (const float*)d_in[15];
    const float* fcA_w  = (const float*)d_in[16];
    const float* fcA_b  = (const float*)d_in[17];
    const float* ln_g   = (const float*)d_in[18];
    const float* ln_b   = (const float*)d_in[19];
    const float* fcB_w  = (const float*)d_in[20];
    const float* fcB_b  = (const float*)d_in[21];
    float* out = (float*)d_out;

    const int* srcp = ei;
    const int* dstp = ei + N_EDGES;

    cudaFuncSetAttribute((const void*)layers_kernel,
                         cudaFuncAttributeMaxDynamicSharedMemorySize, TC_SMEM);

    float* p_hs;
    cudaGetSymbolAddress((void**)&p_hs, g_hs);

    const int SCAN_GRID = (N_NODES + 1023) / 1024;

    prep_kernel<<<PREP_ZERO + PREP_WS + PREP_CS, 256>>>(x, fc1_w, fc2_w);
    hist_kernel<<<(N_EDGES + 511) / 512, 512>>>(dstp);
    scan1_kernel<<<SCAN_GRID, 1024>>>();
    scan3_kernel<<<SCAN_GRID, 1024>>>();
    scatter_kernel<<<(N_EDGES + 511) / 512, 512>>>(srcp, dstp);

    layers_kernel<<<PGRID, LTH, TC_SMEM>>>(
        x, eps, ibn_g, ibn_b,
        fc1_b, bn1_g, bn1_b, fc2_b, bn_g, bn_b, p_hs);

    jk_pool_kernel<<<JKP_BLOCKS, 256>>>(batch, att_w);
    head_kernel<<<N_GRAPHS, 128>>>(pool_w, fcA_w, fcA_b, ln_g, ln_b, fcB_w, fcB_b, out);
}